// round 10
// baseline (speedup 1.0000x reference)
#include <cuda_runtime.h>

#define Bn   64
#define Tn   512
#define DIn  512
#define Hn   1024
#define G4   4096
#define BT   (Bn * Tn)
#define NCTA 128
#define KT   128

// Scratch (device globals: sanctioned, no runtime allocation)
__device__ float g_xproj[(size_t)BT * G4];   // 512 MB: inputs @ W_ih^T + bias
__device__ float g_hbuf[2][Bn * Hn];         // h double buffer
__device__ unsigned g_cnt;                   // grid barrier count (self-restoring)
__device__ volatile unsigned g_gen;          // grid barrier generation (monotonic)

typedef unsigned long long u64;

__device__ __forceinline__ void ffma2(u64 &d, u64 a, u64 b) {
    asm volatile("fma.rn.f32x2 %0, %1, %2, %0;" : "+l"(d) : "l"(a), "l"(b));
}
__device__ __forceinline__ u64 splat2(float x) {
    u64 r; asm("mov.b64 %0, {%1, %1};" : "=l"(r) : "r"(__float_as_uint(x))); return r;
}
__device__ __forceinline__ float2 unpk(u64 v) {
    unsigned lo, hi;
    asm("mov.b64 {%0, %1}, %2;" : "=r"(lo), "=r"(hi) : "l"(v));
    float2 r; r.x = __uint_as_float(lo); r.y = __uint_as_float(hi); return r;
}

__device__ __forceinline__ void grid_sync() {
    __threadfence();          // make this CTA's global writes visible (all threads)
    __syncthreads();
    if (threadIdx.x == 0) {
        unsigned g = g_gen;   // volatile read (L2)
        if (atomicAdd(&g_cnt, 1u) == NCTA - 1) {
            g_cnt = 0;
            __threadfence();
            g_gen = g + 1;    // release
        } else {
            while (g_gen == g) { }
            __threadfence();  // acquire
        }
    }
    __syncthreads();
}

// ---------------------------------------------------------------------------
// Kernel 1: x_proj[b,t,:] = inputs[b,t,:] @ W_ih^T + (b_ih + b_hh)
// C (32768 x 4096) = A (32768 x 512) * W^T (W: 4096 x 512).
// BM=BN=64, BK=16, 256 threads, 4x4 per-thread tile, f32x2 packed FMA.
// ---------------------------------------------------------------------------
__global__ __launch_bounds__(256) void xproj_kernel(
    const float* __restrict__ A, const float* __restrict__ W,
    const float* __restrict__ b_ih, const float* __restrict__ b_hh)
{
    __shared__ float As[16][68];   // [k][m], pad 68 keeps 16B alignment
    __shared__ float Ws[16][68];   // [k][n]

    const int bm  = blockIdx.y * 64;
    const int bn  = blockIdx.x * 64;
    const int tid = threadIdx.x;
    const int tx  = tid & 15;       // n-tile
    const int ty  = tid >> 4;       // m-tile
    const int lr  = tid >> 2;       // loader row 0..63
    const int lc  = (tid & 3) << 2; // loader k-offset 0,4,8,12

    u64 acc[4][2];
#pragma unroll
    for (int i = 0; i < 4; i++) { acc[i][0] = 0ull; acc[i][1] = 0ull; }

    const float* Arow = A + (size_t)(bm + lr) * DIn + lc;
    const float* Wrow = W + (size_t)(bn + lr) * DIn + lc;

    for (int k0 = 0; k0 < DIn; k0 += 16) {
        float4 av = *(const float4*)(Arow + k0);
        float4 wv = *(const float4*)(Wrow + k0);
        __syncthreads();
        As[lc + 0][lr] = av.x; As[lc + 1][lr] = av.y;
        As[lc + 2][lr] = av.z; As[lc + 3][lr] = av.w;
        Ws[lc + 0][lr] = wv.x; Ws[lc + 1][lr] = wv.y;
        Ws[lc + 2][lr] = wv.z; Ws[lc + 3][lr] = wv.w;
        __syncthreads();
#pragma unroll
        for (int kk = 0; kk < 16; kk++) {
            float4 a = *(const float4*)&As[kk][ty << 2];
            ulonglong2 w = *(const ulonglong2*)&Ws[kk][tx << 2];
            u64 s;
            s = splat2(a.x); ffma2(acc[0][0], w.x, s); ffma2(acc[0][1], w.y, s);
            s = splat2(a.y); ffma2(acc[1][0], w.x, s); ffma2(acc[1][1], w.y, s);
            s = splat2(a.z); ffma2(acc[2][0], w.x, s); ffma2(acc[2][1], w.y, s);
            s = splat2(a.w); ffma2(acc[3][0], w.x, s); ffma2(acc[3][1], w.y, s);
        }
    }

    const int n0 = bn + (tx << 2);
    const float bb0 = b_ih[n0 + 0] + b_hh[n0 + 0];
    const float bb1 = b_ih[n0 + 1] + b_hh[n0 + 1];
    const float bb2 = b_ih[n0 + 2] + b_hh[n0 + 2];
    const float bb3 = b_ih[n0 + 3] + b_hh[n0 + 3];
#pragma unroll
    for (int i = 0; i < 4; i++) {
        float2 p0 = unpk(acc[i][0]);
        float2 p1 = unpk(acc[i][1]);
        float4 o = make_float4(p0.x + bb0, p0.y + bb1, p1.x + bb2, p1.y + bb3);
        *(float4*)&g_xproj[(size_t)(bm + (ty << 2) + i) * G4 + n0] = o;
    }
}

// ---------------------------------------------------------------------------
// Kernel 2: persistent LSTM recurrence. 128 CTAs x 256 threads, 1 CTA/SM.
// CTA c owns h-indices j in [8c, 8c+8): W_hh rows {g*1024 + j} (32 rows,
// 128 KB) pinned in smem for all 512 steps. c-state lives in smem. Per step:
//   gates = h_prev @ W_slice^T  (f32x2 FMA, h streamed through smem tiles)
//   + x_proj, activations, write hs/cs, publish h_new, grid barrier.
// ---------------------------------------------------------------------------
__global__ __launch_bounds__(256) void lstm_kernel(
    const float* __restrict__ W_hh, const int* __restrict__ length,
    float* __restrict__ out)
{
    extern __shared__ float sm[];
    float* W_s  = sm;                  // [1024][32] k-major, 32768 floats
    float* h_s  = W_s + 1024 * 32;     // [64][KT]
    float* gbuf = h_s + 64 * KT;       // [64][32]
    float* c_s  = gbuf + 64 * 32;      // [512]
    __shared__ int len_s[Bn];

    const int cta   = blockIdx.x;
    const int tid   = threadIdx.x;
    const int jbase = cta * 8;

    // Load W slice into smem, layout W_s[k*32 + r], r = gate*8 + jj.
    // Conflict-free STS (lane -> r), one-time cost.
    for (int i = tid; i < 32 * 256; i += 256) {
        int r    = i & 31;
        int k4   = (i >> 5) << 2;
        int grow = ((r >> 3) << 10) + jbase + (r & 7);
        float4 v = *(const float4*)&W_hh[(size_t)grow * Hn + k4];
        W_s[(k4 + 0) * 32 + r] = v.x; W_s[(k4 + 1) * 32 + r] = v.y;
        W_s[(k4 + 2) * 32 + r] = v.z; W_s[(k4 + 3) * 32 + r] = v.w;
    }
    for (int i = tid; i < 512; i += 256) c_s[i] = 0.f;
    for (int i = tid; i < 512; i += 256) g_hbuf[0][cta * 512 + i] = 0.f;
    if (tid < Bn) len_s[tid] = length[tid];
    grid_sync();   // h0 = 0 visible everywhere

    const int rq = tid & 7;    // r-quad: r = 4*rq .. 4*rq+3
    const int bp = tid >> 3;   // batch pair: b = 2*bp, 2*bp+1
    const int b0 = bp * 2, b1 = bp * 2 + 1;

    int p = 0;
    for (int t = 0; t < Tn; t++) {
        const float* hprev = g_hbuf[p];
        u64 a00 = 0ull, a01 = 0ull, a10 = 0ull, a11 = 0ull;

        for (int k0 = 0; k0 < Hn; k0 += KT) {
            __syncthreads();
            // Stage h tile (coalesced .cg loads; L1 is stale across steps)
#pragma unroll
            for (int i = 0; i < 8; i++) {
                int lin = i * 256 + tid;
                int bb  = lin >> 5;
                int kq  = (lin & 31) << 2;
                float4 v = __ldcg((const float4*)&hprev[bb * Hn + k0 + kq]);
                *(float4*)&h_s[bb * KT + kq] = v;
            }
            __syncthreads();
            const float* Wp  = W_s + k0 * 32 + (rq << 2);
            const float* hp0 = h_s + b0 * KT;
            const float* hp1 = h_s + b1 * KT;
#pragma unroll 8
            for (int kk = 0; kk < KT; kk++) {
                ulonglong2 w = *(const ulonglong2*)(Wp + kk * 32);
                u64 hh0 = splat2(hp0[kk]);
                u64 hh1 = splat2(hp1[kk]);
                ffma2(a00, w.x, hh0); ffma2(a01, w.y, hh0);
                ffma2(a10, w.x, hh1); ffma2(a11, w.y, hh1);
            }
        }

        // Scatter partial gates to smem for the (b, j) gather
        {
            ulonglong2 v0; v0.x = a00; v0.y = a01;
            *(ulonglong2*)&gbuf[b0 * 32 + (rq << 2)] = v0;
            ulonglong2 v1; v1.x = a10; v1.y = a11;
            *(ulonglong2*)&gbuf[b1 * 32 + (rq << 2)] = v1;
        }
        __syncthreads();

        float* hnext = g_hbuf[p ^ 1];
#pragma unroll
        for (int cc = 0; cc < 2; cc++) {
            int cell = cc * 256 + tid;      // 0..511 = b*8 + jj
            int b  = cell >> 3;
            int jj = cell & 7;
            size_t xb = ((size_t)(b * Tn + t)) * G4 + jbase + jj;
            float gi = gbuf[b * 32 +      jj] + g_xproj[xb];
            float gf = gbuf[b * 32 +  8 + jj] + g_xproj[xb + 1024];
            float gg = gbuf[b * 32 + 16 + jj] + g_xproj[xb + 2048];
            float go = gbuf[b * 32 + 24 + jj] + g_xproj[xb + 3072];
            float co = c_s[cell];
            float si = 1.f / (1.f + __expf(-gi));
            float sf = 1.f / (1.f + __expf(-gf));
            float so = 1.f / (1.f + __expf(-go));
            float tg = tanhf(gg);
            float cn = sf * co + si * tg;
            float hn = so * tanhf(cn);
            c_s[cell] = cn;

            size_t ob = ((size_t)(b * Tn + t)) * Hn + jbase + jj;
            out[ob] = hn;                                   // hs
            out[(size_t)BT * Hn + ob] = cn;                 // cs
            __stcg(&hnext[b * Hn + jbase + jj], hn);
            if (t == len_s[b] - 1) {                        // h_last / c_last
                out[(size_t)2 * BT * Hn + (size_t)b * Hn + jbase + jj] = hn;
                out[(size_t)2 * BT * Hn + (size_t)Bn * Hn + (size_t)b * Hn + jbase + jj] = cn;
            }
        }
        grid_sync();
        p ^= 1;
    }
}

// ---------------------------------------------------------------------------
extern "C" void kernel_launch(void* const* d_in, const int* in_sizes, int n_in,
                              void* d_out, int out_size)
{
    (void)in_sizes; (void)n_in; (void)out_size;
    const float* inputs = (const float*)d_in[0];
    const float* W_ih   = (const float*)d_in[1];
    const float* W_hh   = (const float*)d_in[2];
    const float* b_ih   = (const float*)d_in[3];
    const float* b_hh   = (const float*)d_in[4];
    const int*   length = (const int*)d_in[5];
    float* out = (float*)d_out;

    const int smem_bytes = (1024 * 32 + 64 * KT + 64 * 32 + 512) * 4;  // 174080
    cudaFuncSetAttribute(lstm_kernel,
                         cudaFuncAttributeMaxDynamicSharedMemorySize, smem_bytes);

    dim3 g1(G4 / 64, BT / 64);   // 64 x 512 CTAs
    xproj_kernel<<<g1, 256>>>(inputs, W_ih, b_ih, b_hh);
    lstm_kernel<<<NCTA, 256, smem_bytes>>>(W_hh, length, out);
}

// round 14
// speedup vs baseline: 3.0002x; 3.0002x over previous
#include <cuda_runtime.h>
#include <cuda_bf16.h>
#include <cstdint>

#define Bn   64
#define Tn   512
#define DIn  512
#define Hn   1024
#define G4   4096
#define BT   (Bn * Tn)
#define NCTA 128

// ---------------- device globals (no runtime allocation) ----------------
__device__ float g_xproj[(size_t)BT * G4];        // 512 MB
__device__ __nv_bfloat16 g_hhi[2][Bn * Hn];       // h split-high, double buffered
__device__ __nv_bfloat16 g_hlo[2][Bn * Hn];       // h split-low
__device__ unsigned g_cnt;
__device__ volatile unsigned g_gen;

typedef unsigned long long u64;

// ---------------- scalar f32x2 helpers (xproj kernel) ----------------
__device__ __forceinline__ void ffma2(u64 &d, u64 a, u64 b) {
    asm volatile("fma.rn.f32x2 %0, %1, %2, %0;" : "+l"(d) : "l"(a), "l"(b));
}
__device__ __forceinline__ u64 splat2(float x) {
    u64 r; asm("mov.b64 %0, {%1, %1};" : "=l"(r) : "r"(__float_as_uint(x))); return r;
}
__device__ __forceinline__ float2 unpk(u64 v) {
    unsigned lo, hi;
    asm("mov.b64 {%0, %1}, %2;" : "=r"(lo), "=r"(hi) : "l"(v));
    float2 r; r.x = __uint_as_float(lo); r.y = __uint_as_float(hi); return r;
}

__device__ __forceinline__ void grid_sync() {
    __threadfence();
    __syncthreads();
    if (threadIdx.x == 0) {
        unsigned g = g_gen;
        if (atomicAdd(&g_cnt, 1u) == NCTA - 1) {
            g_cnt = 0;
            __threadfence();
            g_gen = g + 1;
        } else {
            while (g_gen == g) { }
            __threadfence();
        }
    }
    __syncthreads();
}

// ---------------- mma.sync helpers (standard PTX, sm_80+) ----------------
__device__ __forceinline__ uint32_t smem_u32(const void* p) {
    uint32_t a;
    asm("{ .reg .u64 t; cvta.to.shared.u64 t, %1; cvt.u32.u64 %0, t; }" : "=r"(a) : "l"(p));
    return a;
}
__device__ __forceinline__ void ldsm4(uint32_t addr, uint32_t r[4]) {
    asm volatile("ldmatrix.sync.aligned.m8n8.x4.shared.b16 {%0,%1,%2,%3}, [%4];"
                 : "=r"(r[0]), "=r"(r[1]), "=r"(r[2]), "=r"(r[3]) : "r"(addr));
}
__device__ __forceinline__ void mma16816(float* d, const uint32_t* a, uint32_t b0, uint32_t b1) {
    asm volatile("mma.sync.aligned.m16n8k16.row.col.f32.bf16.bf16.f32 "
                 "{%0,%1,%2,%3}, {%4,%5,%6,%7}, {%8,%9}, {%0,%1,%2,%3};"
                 : "+f"(d[0]), "+f"(d[1]), "+f"(d[2]), "+f"(d[3])
                 : "r"(a[0]), "r"(a[1]), "r"(a[2]), "r"(a[3]), "r"(b0), "r"(b1));
}

// ---------------------------------------------------------------------------
// Kernel 1: x_proj = inputs @ W_ih^T + (b_ih + b_hh)   (unchanged, known good)
// ---------------------------------------------------------------------------
__global__ __launch_bounds__(256) void xproj_kernel(
    const float* __restrict__ A, const float* __restrict__ W,
    const float* __restrict__ b_ih, const float* __restrict__ b_hh)
{
    __shared__ float As[16][68];
    __shared__ float Ws[16][68];

    const int bm  = blockIdx.y * 64;
    const int bn  = blockIdx.x * 64;
    const int tid = threadIdx.x;
    const int tx  = tid & 15;
    const int ty  = tid >> 4;
    const int lr  = tid >> 2;
    const int lc  = (tid & 3) << 2;

    u64 acc[4][2];
#pragma unroll
    for (int i = 0; i < 4; i++) { acc[i][0] = 0ull; acc[i][1] = 0ull; }

    const float* Arow = A + (size_t)(bm + lr) * DIn + lc;
    const float* Wrow = W + (size_t)(bn + lr) * DIn + lc;

    for (int k0 = 0; k0 < DIn; k0 += 16) {
        float4 av = *(const float4*)(Arow + k0);
        float4 wv = *(const float4*)(Wrow + k0);
        __syncthreads();
        As[lc + 0][lr] = av.x; As[lc + 1][lr] = av.y;
        As[lc + 2][lr] = av.z; As[lc + 3][lr] = av.w;
        Ws[lc + 0][lr] = wv.x; Ws[lc + 1][lr] = wv.y;
        Ws[lc + 2][lr] = wv.z; Ws[lc + 3][lr] = wv.w;
        __syncthreads();
#pragma unroll
        for (int kk = 0; kk < 16; kk++) {
            float4 a = *(const float4*)&As[kk][ty << 2];
            ulonglong2 w = *(const ulonglong2*)&Ws[kk][tx << 2];
            u64 s;
            s = splat2(a.x); ffma2(acc[0][0], w.x, s); ffma2(acc[0][1], w.y, s);
            s = splat2(a.y); ffma2(acc[1][0], w.x, s); ffma2(acc[1][1], w.y, s);
            s = splat2(a.z); ffma2(acc[2][0], w.x, s); ffma2(acc[2][1], w.y, s);
            s = splat2(a.w); ffma2(acc[3][0], w.x, s); ffma2(acc[3][1], w.y, s);
        }
    }

    const int n0 = bn + (tx << 2);
    const float bb0 = b_ih[n0 + 0] + b_hh[n0 + 0];
    const float bb1 = b_ih[n0 + 1] + b_hh[n0 + 1];
    const float bb2 = b_ih[n0 + 2] + b_hh[n0 + 2];
    const float bb3 = b_ih[n0 + 3] + b_hh[n0 + 3];
#pragma unroll
    for (int i = 0; i < 4; i++) {
        float2 p0 = unpk(acc[i][0]);
        float2 p1 = unpk(acc[i][1]);
        float4 o = make_float4(p0.x + bb0, p0.y + bb1, p1.x + bb2, p1.y + bb3);
        *(float4*)&g_xproj[(size_t)(bm + (ty << 2) + i) * G4 + n0] = o;
    }
}

// ---------------------------------------------------------------------------
// Kernel 2: persistent HMMA (mma.sync bf16) LSTM recurrence.
// 128 CTAs x 256 threads, 1 CTA/SM. CTA owns 32 gate rows (8 h-indices).
// Per step: D[64x32] = A[64x1024] @ B[32x1024]^T, bf16 Ootomo split
// (hi*hi + hi*lo + lo*hi), fp32 accumulate in registers.
// Warp w: m-tile (w&3)*16 rows, n-half (w>>2)*16 gate cols, full k.
//
// smem layout (bytes), dynamic:
//   W_hi : 32 rows x 2064   [0      .. 66048)
//   W_lo : 32 rows x 2064   [66048  .. 132096)
//   A    : 2 bufs x {hi,lo} x (64 rows x 272)  [132096 .. 201728)
//   gbuf : 64 x 32 f32      [201728 .. 209920)
//   c_s  : 512 f32          [209920 .. 211968)
// Row pads (+16B) make ldmatrix conflict-free (stride % 128 == 16).
// ---------------------------------------------------------------------------
#define WROW  2064
#define WSZ   (32 * WROW)          // 66048
#define AROW  272
#define ASZ   (64 * AROW)          // 17408
#define SM_W  0
#define SM_A  (2 * WSZ)            // 132096
#define SM_GBUF (SM_A + 4 * ASZ)   // 201728
#define SM_CS   (SM_GBUF + 8192)   // 209920
#define SM_TOTAL (SM_CS + 2048)    // 211968

__global__ __launch_bounds__(256, 1) void lstm_mma_kernel(
    const float* __restrict__ W_hh, const int* __restrict__ length,
    float* __restrict__ out)
{
    extern __shared__ char smem[];
    const uint32_t sb = smem_u32(smem);
    __shared__ int len_s[Bn];

    const int tid   = threadIdx.x;
    const int wid   = tid >> 5;
    const int lane  = tid & 31;
    const int cta   = blockIdx.x;
    const int jbase = cta * 8;

    float* gbuf = (float*)(smem + SM_GBUF);
    float* c_s  = (float*)(smem + SM_CS);

    // ---- init: load W slice, split to bf16 hi/lo (padded rows) ----
    {
        const int n    = tid >> 3;                       // 0..31 gate row
        const int grow = ((n >> 3) << 10) + jbase + (n & 7);
        const int cb   = (tid & 7) * 128;
        const float* wrow = W_hh + (size_t)grow * Hn + cb;
        char* whi = smem + SM_W + n * WROW + cb * 2;
        char* wlo = whi + WSZ;
        for (int k4 = 0; k4 < 128; k4 += 4) {
            float4 w = *(const float4*)(wrow + k4);
            __nv_bfloat16 h0 = __float2bfloat16(w.x);
            __nv_bfloat16 h1 = __float2bfloat16(w.y);
            __nv_bfloat16 h2 = __float2bfloat16(w.z);
            __nv_bfloat16 h3 = __float2bfloat16(w.w);
            __nv_bfloat16 l0 = __float2bfloat16(w.x - __bfloat162float(h0));
            __nv_bfloat16 l1 = __float2bfloat16(w.y - __bfloat162float(h1));
            __nv_bfloat16 l2 = __float2bfloat16(w.z - __bfloat162float(h2));
            __nv_bfloat16 l3 = __float2bfloat16(w.w - __bfloat162float(h3));
            ushort4 vh = make_ushort4(__bfloat16_as_ushort(h0), __bfloat16_as_ushort(h1),
                                      __bfloat16_as_ushort(h2), __bfloat16_as_ushort(h3));
            ushort4 vl = make_ushort4(__bfloat16_as_ushort(l0), __bfloat16_as_ushort(l1),
                                      __bfloat16_as_ushort(l2), __bfloat16_as_ushort(l3));
            *(ushort4*)(whi + k4 * 2) = vh;
            *(ushort4*)(wlo + k4 * 2) = vl;
        }
    }
    for (int i = tid; i < 512; i += 256) c_s[i] = 0.f;
    for (int i = tid; i < 512; i += 256) {
        int b = i >> 3, jj = i & 7;
        g_hhi[0][b * Hn + jbase + jj] = __float2bfloat16(0.f);
        g_hlo[0][b * Hn + jbase + jj] = __float2bfloat16(0.f);
    }
    if (tid < Bn) len_s[tid] = length[tid];
    grid_sync();   // h0 visible everywhere, W resident

    // ---- warp tile mapping ----
    const int mt = wid & 3;            // m-tile: rows mt*16 .. +15
    const int nh = wid >> 2;           // n-half: cols nh*16 .. +15
    const int qr = lane >> 3;          // ldmatrix quadrant
    const int lr8 = lane & 7;
    // A frag addr: row = mt*16 + lr8 + (qr&1)*8 ; kbyte += (qr>>1)*16
    const uint32_t arow_off = (uint32_t)((mt * 16 + lr8 + (qr & 1) * 8) * AROW + (qr >> 1) * 16);
    // B frag addr: row = nh*16 + lr8 + (qr>>1)*8 ; kbyte += (qr&1)*16
    const uint32_t brow_off = (uint32_t)((nh * 16 + lr8 + (qr >> 1) * 8) * WROW + (qr & 1) * 16);

    // ---- stage mapping: thread -> (row, 32-col segment) of A chunk ----
    const int srow = tid >> 2;             // 0..63 batch row
    const int scol = (tid & 3) * 32;       // bf16 col within 128-chunk
    const uint32_t s_off = (uint32_t)(srow * AROW + scol * 2);

    int p = 0;

    for (int t = 0; t < Tn; t++) {
        const __nv_bfloat16* Hhi = g_hhi[p];
        const __nv_bfloat16* Hlo = g_hlo[p];
        const size_t gbase = (size_t)srow * Hn + scol;

        // stage chunk 0 -> buf 0
        {
            const char* gh = (const char*)(Hhi + gbase);
            const char* gl = (const char*)(Hlo + gbase);
            char* sh = smem + SM_A + s_off;
            char* sl = sh + ASZ;
#pragma unroll
            for (int q = 0; q < 4; q++) {
                *(uint4*)(sh + q * 16) = __ldcg((const uint4*)(gh + q * 16));
                *(uint4*)(sl + q * 16) = __ldcg((const uint4*)(gl + q * 16));
            }
        }
        __syncthreads();

        float d0[4] = {0.f, 0.f, 0.f, 0.f};
        float d1[4] = {0.f, 0.f, 0.f, 0.f};

        for (int c = 0; c < 8; c++) {
            // prefetch next chunk into registers (overlaps MMAs)
            uint4 rh[4], rl[4];
            if (c < 7) {
                const char* gh = (const char*)(Hhi + gbase + (c + 1) * 128);
                const char* gl = (const char*)(Hlo + gbase + (c + 1) * 128);
#pragma unroll
                for (int q = 0; q < 4; q++) {
                    rh[q] = __ldcg((const uint4*)(gh + q * 16));
                    rl[q] = __ldcg((const uint4*)(gl + q * 16));
                }
            }
            // compute chunk c (k = c*128 .. +127)
            const uint32_t a_hi = sb + SM_A + (uint32_t)((c & 1) * 2 * ASZ) + arow_off;
            const uint32_t a_lo = a_hi + ASZ;
            const uint32_t b_hi = sb + SM_W + brow_off + (uint32_t)(c * 256);
            const uint32_t b_lo = b_hi + WSZ;
#pragma unroll
            for (int kk = 0; kk < 8; kk++) {
                uint32_t ah[4], al[4], bh[4], bl[4];
                ldsm4(a_hi + kk * 32, ah);
                ldsm4(a_lo + kk * 32, al);
                ldsm4(b_hi + kk * 32, bh);
                ldsm4(b_lo + kk * 32, bl);
                mma16816(d0, ah, bh[0], bh[1]); mma16816(d1, ah, bh[2], bh[3]);
                mma16816(d0, ah, bl[0], bl[1]); mma16816(d1, ah, bl[2], bl[3]);
                mma16816(d0, al, bh[0], bh[1]); mma16816(d1, al, bh[2], bh[3]);
            }
            if (c < 7) {
                char* sh = smem + SM_A + (size_t)(((c + 1) & 1) * 2 * ASZ) + s_off;
                char* sl = sh + ASZ;
#pragma unroll
                for (int q = 0; q < 4; q++) {
                    *(uint4*)(sh + q * 16) = rh[q];
                    *(uint4*)(sl + q * 16) = rl[q];
                }
            }
            __syncthreads();
        }

        // ---- scatter D frags to gbuf[64][32] ----
        {
            const int gr = mt * 16 + (lane >> 2);
            const int gc = nh * 16 + (lane & 3) * 2;
            *(float2*)&gbuf[gr * 32 + gc]           = make_float2(d0[0], d0[1]);
            *(float2*)&gbuf[(gr + 8) * 32 + gc]     = make_float2(d0[2], d0[3]);
            *(float2*)&gbuf[gr * 32 + gc + 8]       = make_float2(d1[0], d1[1]);
            *(float2*)&gbuf[(gr + 8) * 32 + gc + 8] = make_float2(d1[2], d1[3]);
        }
        __syncthreads();

        // ---- epilogue: 512 cells (b, jj) over 256 threads ----
#pragma unroll
        for (int cc = 0; cc < 2; cc++) {
            int cell = cc * 256 + tid;
            int b  = cell >> 3;
            int jj = cell & 7;
            size_t xb = ((size_t)(b * Tn + t)) * G4 + jbase + jj;
            float gi = gbuf[b * 32 +      jj] + g_xproj[xb];
            float gf = gbuf[b * 32 +  8 + jj] + g_xproj[xb + 1024];
            float gg = gbuf[b * 32 + 16 + jj] + g_xproj[xb + 2048];
            float go = gbuf[b * 32 + 24 + jj] + g_xproj[xb + 3072];
            float co = c_s[cell];
            float si = 1.f / (1.f + __expf(-gi));
            float sf = 1.f / (1.f + __expf(-gf));
            float so = 1.f / (1.f + __expf(-go));
            float tg = tanhf(gg);
            float cn = sf * co + si * tg;
            float hn = so * tanhf(cn);
            c_s[cell] = cn;

            size_t ob = ((size_t)(b * Tn + t)) * Hn + jbase + jj;
            out[ob] = hn;                                   // hs
            out[(size_t)BT * Hn + ob] = cn;                 // cs

            __nv_bfloat16 hh = __float2bfloat16(hn);
            __nv_bfloat16 hl = __float2bfloat16(hn - __bfloat162float(hh));
            g_hhi[p ^ 1][b * Hn + jbase + jj] = hh;
            g_hlo[p ^ 1][b * Hn + jbase + jj] = hl;

            if (t == len_s[b] - 1) {                        // h_last / c_last
                out[(size_t)2 * BT * Hn + (size_t)b * Hn + jbase + jj] = hn;
                out[(size_t)2 * BT * Hn + (size_t)Bn * Hn + (size_t)b * Hn + jbase + jj] = cn;
            }
        }
        grid_sync();
        p ^= 1;
    }
}

// ---------------------------------------------------------------------------
extern "C" void kernel_launch(void* const* d_in, const int* in_sizes, int n_in,
                              void* d_out, int out_size)
{
    (void)in_sizes; (void)n_in; (void)out_size;
    const float* inputs = (const float*)d_in[0];
    const float* W_ih   = (const float*)d_in[1];
    const float* W_hh   = (const float*)d_in[2];
    const float* b_ih   = (const float*)d_in[3];
    const float* b_hh   = (const float*)d_in[4];
    const int*   length = (const int*)d_in[5];
    float* out = (float*)d_out;

    cudaFuncSetAttribute(lstm_mma_kernel,
                         cudaFuncAttributeMaxDynamicSharedMemorySize, SM_TOTAL);

    dim3 g1(G4 / 64, BT / 64);   // 64 x 512 CTAs
    xproj_kernel<<<g1, 256>>>(inputs, W_ih, b_ih, b_hh);
    lstm_mma_kernel<<<NCTA, 256, SM_TOTAL>>>(W_hh, length, out);
}

// round 15
// speedup vs baseline: 3.5969x; 1.1989x over previous
#include <cuda_runtime.h>
#include <cuda_bf16.h>
#include <cstdint>

#define Bn   64
#define Tn   512
#define DIn  512
#define Hn   1024
#define G4   4096
#define BT   (Bn * Tn)
#define NCTA 128

// ---------------- device globals (no runtime allocation) ----------------
__device__ float g_xproj[(size_t)BT * G4];        // 512 MB
__device__ __nv_bfloat16 g_hhi[2][Bn * Hn];       // h split-high, double buffered
__device__ __nv_bfloat16 g_hlo[2][Bn * Hn];       // h split-low
__device__ __nv_bfloat16 g_ahi[(size_t)BT * DIn]; // inputs split-high
__device__ __nv_bfloat16 g_alo[(size_t)BT * DIn]; // inputs split-low
__device__ __nv_bfloat16 g_whi[(size_t)G4 * DIn]; // W_ih split-high
__device__ __nv_bfloat16 g_wlo[(size_t)G4 * DIn]; // W_ih split-low
__device__ unsigned g_cnt;
__device__ volatile unsigned g_gen;

typedef unsigned long long u64;

__device__ __forceinline__ void grid_sync() {
    __threadfence();
    __syncthreads();
    if (threadIdx.x == 0) {
        unsigned g = g_gen;
        if (atomicAdd(&g_cnt, 1u) == NCTA - 1) {
            g_cnt = 0;
            __threadfence();
            g_gen = g + 1;
        } else {
            while (g_gen == g) { }
            __threadfence();
        }
    }
    __syncthreads();
}

// ---------------- mma.sync helpers (standard PTX, sm_80+) ----------------
__device__ __forceinline__ uint32_t smem_u32(const void* p) {
    uint32_t a;
    asm("{ .reg .u64 t; cvta.to.shared.u64 t, %1; cvt.u32.u64 %0, t; }" : "=r"(a) : "l"(p));
    return a;
}
__device__ __forceinline__ void ldsm4(uint32_t addr, uint32_t r[4]) {
    asm volatile("ldmatrix.sync.aligned.m8n8.x4.shared.b16 {%0,%1,%2,%3}, [%4];"
                 : "=r"(r[0]), "=r"(r[1]), "=r"(r[2]), "=r"(r[3]) : "r"(addr));
}
__device__ __forceinline__ void mma16816(float* d, const uint32_t* a, uint32_t b0, uint32_t b1) {
    asm volatile("mma.sync.aligned.m16n8k16.row.col.f32.bf16.bf16.f32 "
                 "{%0,%1,%2,%3}, {%4,%5,%6,%7}, {%8,%9}, {%0,%1,%2,%3};"
                 : "+f"(d[0]), "+f"(d[1]), "+f"(d[2]), "+f"(d[3])
                 : "r"(a[0]), "r"(a[1]), "r"(a[2]), "r"(a[3]), "r"(b0), "r"(b1));
}
__device__ __forceinline__ void cpasync16(uint32_t s, const void* g) {
    asm volatile("cp.async.cg.shared.global [%0], [%1], 16;" :: "r"(s), "l"(g) : "memory");
}
#define CP_COMMIT() asm volatile("cp.async.commit_group;" ::: "memory")
#define CP_WAIT(n)  asm volatile("cp.async.wait_group %0;" :: "n"(n) : "memory")

// ---------------------------------------------------------------------------
// Kernel 0: element-wise fp32 -> bf16 hi/lo split
// ---------------------------------------------------------------------------
__global__ __launch_bounds__(256) void split_kernel(
    const float* __restrict__ src, __nv_bfloat16* __restrict__ hi,
    __nv_bfloat16* __restrict__ lo, int n4)
{
    int i = blockIdx.x * blockDim.x + threadIdx.x;
    if (i >= n4) return;
    float4 v = ((const float4*)src)[i];
    __nv_bfloat16 h0 = __float2bfloat16(v.x);
    __nv_bfloat16 h1 = __float2bfloat16(v.y);
    __nv_bfloat16 h2 = __float2bfloat16(v.z);
    __nv_bfloat16 h3 = __float2bfloat16(v.w);
    ushort4 vh = make_ushort4(__bfloat16_as_ushort(h0), __bfloat16_as_ushort(h1),
                              __bfloat16_as_ushort(h2), __bfloat16_as_ushort(h3));
    __nv_bfloat16 l0 = __float2bfloat16(v.x - __bfloat162float(h0));
    __nv_bfloat16 l1 = __float2bfloat16(v.y - __bfloat162float(h1));
    __nv_bfloat16 l2 = __float2bfloat16(v.z - __bfloat162float(h2));
    __nv_bfloat16 l3 = __float2bfloat16(v.w - __bfloat162float(h3));
    ushort4 vl = make_ushort4(__bfloat16_as_ushort(l0), __bfloat16_as_ushort(l1),
                              __bfloat16_as_ushort(l2), __bfloat16_as_ushort(l3));
    ((ushort4*)hi)[i] = vh;
    ((ushort4*)lo)[i] = vl;
}

// ---------------------------------------------------------------------------
// Kernel 1: x_proj = inputs @ W_ih^T + (b_ih + b_hh), bf16 3-term HMMA.
// CTA tile 128(m) x 64(n), K chunks of 64, cp.async double-buffered.
// 8 warps: warp (wr = wid>>1, wc = wid&1) owns m32 x n32.
// Row pad +16B (144B rows) -> conflict-free ldmatrix.
// smem: A[2 buf][hi,lo] 128x144 = 73728; W[2][hi,lo] 64x144 = 36864;
//       bias 256 -> 110848 B.
// ---------------------------------------------------------------------------
#define XAROW 144
#define XASPL (128 * XAROW)            // 18432
#define XWSPL (64 * XAROW)             // 9216
#define XSM_A 0
#define XSM_W (4 * XASPL)              // 73728
#define XSM_B (XSM_W + 4 * XWSPL)      // 110592
#define XSM_TOTAL (XSM_B + 256)        // 110848

__global__ __launch_bounds__(256) void xproj_mma_kernel(
    const float* __restrict__ b_ih, const float* __restrict__ b_hh)
{
    extern __shared__ char smem[];
    const uint32_t sb = smem_u32(smem);
    const int tid  = threadIdx.x;
    const int wid  = tid >> 5;
    const int lane = tid & 31;
    const int bn   = blockIdx.x * 64;    // n fastest: 64 CTAs share the A tile
    const int bm   = blockIdx.y * 128;

    float* bias_s = (float*)(smem + XSM_B);
    if (tid < 64) bias_s[tid] = b_ih[bn + tid] + b_hh[bn + tid];

    // stage mappings
    const int ar  = tid >> 1;                       // A row 0..127 (2 segs/thread x2 iters)
    const int as0 = (tid & 1) * 4;                  // seg pairs handled below
    (void)as0;

    // A: 128 rows x 8 segs(16B) = 1024 per split -> 4 per thread
    // W: 64 rows x 8 segs = 512 per split -> 2 per thread
    auto stage = [&](int c, int buf) {
        char* abase_h = smem + XSM_A + buf * 2 * XASPL;
        char* abase_l = abase_h + XASPL;
        char* wbase_h = smem + XSM_W + buf * 2 * XWSPL;
        char* wbase_l = wbase_h + XWSPL;
        const __nv_bfloat16* gah = g_ahi + (size_t)bm * DIn + c * 64;
        const __nv_bfloat16* gal = g_alo + (size_t)bm * DIn + c * 64;
        const __nv_bfloat16* gwh = g_whi + (size_t)bn * DIn + c * 64;
        const __nv_bfloat16* gwl = g_wlo + (size_t)bn * DIn + c * 64;
#pragma unroll
        for (int i = 0; i < 4; i++) {
            int idx = i * 256 + tid;
            int row = idx >> 3, seg = idx & 7;
            uint32_t so = (uint32_t)(row * XAROW + seg * 16);
            size_t   go = (size_t)row * DIn + seg * 8;
            cpasync16(sb + XSM_A + buf * 2 * XASPL + so, gah + go);
            cpasync16(sb + XSM_A + buf * 2 * XASPL + XASPL + so, gal + go);
        }
#pragma unroll
        for (int i = 0; i < 2; i++) {
            int idx = i * 256 + tid;
            int row = idx >> 3, seg = idx & 7;
            uint32_t so = (uint32_t)(row * XAROW + seg * 16);
            size_t   go = (size_t)row * DIn + seg * 8;
            cpasync16(sb + XSM_W + buf * 2 * XWSPL + so, gwh + go);
            cpasync16(sb + XSM_W + buf * 2 * XWSPL + XWSPL + so, gwl + go);
        }
        (void)abase_h; (void)abase_l; (void)wbase_h; (void)wbase_l;
    };

    // warp tile mapping (identical math to lstm kernel, proven)
    const int wr = wid >> 1;           // m: wr*32
    const int wc = wid & 1;            // n: wc*32
    const int qr = lane >> 3;
    const int lr8 = lane & 7;
    const uint32_t arow_off = (uint32_t)((wr * 32 + lr8 + (qr & 1) * 8) * XAROW + (qr >> 1) * 16);
    const uint32_t brow_off = (uint32_t)((wc * 32 + lr8 + (qr >> 1) * 8) * XAROW + (qr & 1) * 16);

    float d[2][4][4];
#pragma unroll
    for (int a = 0; a < 2; a++)
#pragma unroll
        for (int j = 0; j < 4; j++)
#pragma unroll
            for (int q = 0; q < 4; q++) d[a][j][q] = 0.f;

    stage(0, 0);
    CP_COMMIT();

    for (int c = 0; c < 8; c++) {
        const int buf = c & 1;
        if (c < 7) { stage(c + 1, buf ^ 1); CP_COMMIT(); CP_WAIT(1); }
        else       { CP_WAIT(0); }
        __syncthreads();

        const uint32_t aH = sb + XSM_A + buf * 2 * XASPL + arow_off;
        const uint32_t aL = aH + XASPL;
        const uint32_t bH = sb + XSM_W + buf * 2 * XWSPL + brow_off;
        const uint32_t bL = bH + XWSPL;
#pragma unroll
        for (int kk = 0; kk < 4; kk++) {
            uint32_t ah0[4], ah1[4], al0[4], al1[4];
            uint32_t bh0[4], bh1[4], bl0[4], bl1[4];
            ldsm4(aH + kk * 32, ah0);
            ldsm4(aH + 16 * XAROW + kk * 32, ah1);
            ldsm4(aL + kk * 32, al0);
            ldsm4(aL + 16 * XAROW + kk * 32, al1);
            ldsm4(bH + kk * 32, bh0);
            ldsm4(bH + 16 * XAROW + kk * 32, bh1);
            ldsm4(bL + kk * 32, bl0);
            ldsm4(bL + 16 * XAROW + kk * 32, bl1);

            // term hi*hi
            mma16816(d[0][0], ah0, bh0[0], bh0[1]); mma16816(d[0][1], ah0, bh0[2], bh0[3]);
            mma16816(d[0][2], ah0, bh1[0], bh1[1]); mma16816(d[0][3], ah0, bh1[2], bh1[3]);
            mma16816(d[1][0], ah1, bh0[0], bh0[1]); mma16816(d[1][1], ah1, bh0[2], bh0[3]);
            mma16816(d[1][2], ah1, bh1[0], bh1[1]); mma16816(d[1][3], ah1, bh1[2], bh1[3]);
            // term hi*lo
            mma16816(d[0][0], ah0, bl0[0], bl0[1]); mma16816(d[0][1], ah0, bl0[2], bl0[3]);
            mma16816(d[0][2], ah0, bl1[0], bl1[1]); mma16816(d[0][3], ah0, bl1[2], bl1[3]);
            mma16816(d[1][0], ah1, bl0[0], bl0[1]); mma16816(d[1][1], ah1, bl0[2], bl0[3]);
            mma16816(d[1][2], ah1, bl1[0], bl1[1]); mma16816(d[1][3], ah1, bl1[2], bl1[3]);
            // term lo*hi
            mma16816(d[0][0], al0, bh0[0], bh0[1]); mma16816(d[0][1], al0, bh0[2], bh0[3]);
            mma16816(d[0][2], al0, bh1[0], bh1[1]); mma16816(d[0][3], al0, bh1[2], bh1[3]);
            mma16816(d[1][0], al1, bh0[0], bh0[1]); mma16816(d[1][1], al1, bh0[2], bh0[3]);
            mma16816(d[1][2], al1, bh1[0], bh1[1]); mma16816(d[1][3], al1, bh1[2], bh1[3]);
        }
        __syncthreads();
    }

    // epilogue: +bias, fp32 stores
    const int r0 = lane >> 2;
    const int c0 = (lane & 3) * 2;
#pragma unroll
    for (int a = 0; a < 2; a++) {
#pragma unroll
        for (int j = 0; j < 4; j++) {
            int nloc = wc * 32 + j * 8 + c0;
            float bb0 = bias_s[nloc], bb1 = bias_s[nloc + 1];
            size_t row = (size_t)(bm + wr * 32 + a * 16 + r0);
            float* p0 = &g_xproj[row * G4 + bn + nloc];
            float* p1 = &g_xproj[(row + 8) * G4 + bn + nloc];
            *(float2*)p0 = make_float2(d[a][j][0] + bb0, d[a][j][1] + bb1);
            *(float2*)p1 = make_float2(d[a][j][2] + bb0, d[a][j][3] + bb1);
        }
    }
}

// ---------------------------------------------------------------------------
// Kernel 2: persistent HMMA LSTM recurrence (R14 kernel + split accumulators
// for 4 independent MMA chains per warp).
// ---------------------------------------------------------------------------
#define WROW  2064
#define WSZ   (32 * WROW)          // 66048
#define AROW  272
#define ASZ   (64 * AROW)          // 17408
#define SM_W  0
#define SM_A  (2 * WSZ)            // 132096
#define SM_GBUF (SM_A + 4 * ASZ)   // 201728
#define SM_CS   (SM_GBUF + 8192)   // 209920
#define SM_TOTAL (SM_CS + 2048)    // 211968

__global__ __launch_bounds__(256, 1) void lstm_mma_kernel(
    const float* __restrict__ W_hh, const int* __restrict__ length,
    float* __restrict__ out)
{
    extern __shared__ char smem[];
    const uint32_t sb = smem_u32(smem);
    __shared__ int len_s[Bn];

    const int tid   = threadIdx.x;
    const int wid   = tid >> 5;
    const int lane  = tid & 31;
    const int cta   = blockIdx.x;
    const int jbase = cta * 8;

    float* gbuf = (float*)(smem + SM_GBUF);
    float* c_s  = (float*)(smem + SM_CS);

    // ---- init: load W slice, split to bf16 hi/lo (padded rows) ----
    {
        const int n    = tid >> 3;
        const int grow = ((n >> 3) << 10) + jbase + (n & 7);
        const int cb   = (tid & 7) * 128;
        const float* wrow = W_hh + (size_t)grow * Hn + cb;
        char* whi = smem + SM_W + n * WROW + cb * 2;
        char* wlo = whi + WSZ;
        for (int k4 = 0; k4 < 128; k4 += 4) {
            float4 w = *(const float4*)(wrow + k4);
            __nv_bfloat16 h0 = __float2bfloat16(w.x);
            __nv_bfloat16 h1 = __float2bfloat16(w.y);
            __nv_bfloat16 h2 = __float2bfloat16(w.z);
            __nv_bfloat16 h3 = __float2bfloat16(w.w);
            __nv_bfloat16 l0 = __float2bfloat16(w.x - __bfloat162float(h0));
            __nv_bfloat16 l1 = __float2bfloat16(w.y - __bfloat162float(h1));
            __nv_bfloat16 l2 = __float2bfloat16(w.z - __bfloat162float(h2));
            __nv_bfloat16 l3 = __float2bfloat16(w.w - __bfloat162float(h3));
            ushort4 vh = make_ushort4(__bfloat16_as_ushort(h0), __bfloat16_as_ushort(h1),
                                      __bfloat16_as_ushort(h2), __bfloat16_as_ushort(h3));
            ushort4 vl = make_ushort4(__bfloat16_as_ushort(l0), __bfloat16_as_ushort(l1),
                                      __bfloat16_as_ushort(l2), __bfloat16_as_ushort(l3));
            *(ushort4*)(whi + k4 * 2) = vh;
            *(ushort4*)(wlo + k4 * 2) = vl;
        }
    }
    for (int i = tid; i < 512; i += 256) c_s[i] = 0.f;
    for (int i = tid; i < 512; i += 256) {
        int b = i >> 3, jj = i & 7;
        g_hhi[0][b * Hn + jbase + jj] = __float2bfloat16(0.f);
        g_hlo[0][b * Hn + jbase + jj] = __float2bfloat16(0.f);
    }
    if (tid < Bn) len_s[tid] = length[tid];
    grid_sync();

    const int mt = wid & 3;
    const int nh = wid >> 2;
    const int qr = lane >> 3;
    const int lr8 = lane & 7;
    const uint32_t arow_off = (uint32_t)((mt * 16 + lr8 + (qr & 1) * 8) * AROW + (qr >> 1) * 16);
    const uint32_t brow_off = (uint32_t)((nh * 16 + lr8 + (qr >> 1) * 8) * WROW + (qr & 1) * 16);

    const int srow = tid >> 2;
    const int scol = (tid & 3) * 32;
    const uint32_t s_off = (uint32_t)(srow * AROW + scol * 2);

    int p = 0;

    for (int t = 0; t < Tn; t++) {
        const __nv_bfloat16* Hhi = g_hhi[p];
        const __nv_bfloat16* Hlo = g_hlo[p];
        const size_t gbase = (size_t)srow * Hn + scol;

        {
            const char* gh = (const char*)(Hhi + gbase);
            const char* gl = (const char*)(Hlo + gbase);
            char* sh = smem + SM_A + s_off;
            char* sl = sh + ASZ;
#pragma unroll
            for (int q = 0; q < 4; q++) {
                *(uint4*)(sh + q * 16) = __ldcg((const uint4*)(gh + q * 16));
                *(uint4*)(sl + q * 16) = __ldcg((const uint4*)(gl + q * 16));
            }
        }
        __syncthreads();

        float d0a[4] = {0.f, 0.f, 0.f, 0.f};
        float d0b[4] = {0.f, 0.f, 0.f, 0.f};
        float d1a[4] = {0.f, 0.f, 0.f, 0.f};
        float d1b[4] = {0.f, 0.f, 0.f, 0.f};

        for (int c = 0; c < 8; c++) {
            uint4 rh[4], rl[4];
            if (c < 7) {
                const char* gh = (const char*)(Hhi + gbase + (c + 1) * 128);
                const char* gl = (const char*)(Hlo + gbase + (c + 1) * 128);
#pragma unroll
                for (int q = 0; q < 4; q++) {
                    rh[q] = __ldcg((const uint4*)(gh + q * 16));
                    rl[q] = __ldcg((const uint4*)(gl + q * 16));
                }
            }
            const uint32_t a_hi = sb + SM_A + (uint32_t)((c & 1) * 2 * ASZ) + arow_off;
            const uint32_t a_lo = a_hi + ASZ;
            const uint32_t b_hi = sb + SM_W + brow_off + (uint32_t)(c * 256);
            const uint32_t b_lo = b_hi + WSZ;
#pragma unroll
            for (int kk = 0; kk < 8; kk++) {
                uint32_t ah[4], al[4], bh[4], bl[4];
                ldsm4(a_hi + kk * 32, ah);
                ldsm4(a_lo + kk * 32, al);
                ldsm4(b_hi + kk * 32, bh);
                ldsm4(b_lo + kk * 32, bl);
                mma16816(d0a, ah, bh[0], bh[1]); mma16816(d1a, ah, bh[2], bh[3]);
                mma16816(d0b, ah, bl[0], bl[1]); mma16816(d1b, ah, bl[2], bl[3]);
                mma16816(d0b, al, bh[0], bh[1]); mma16816(d1b, al, bh[2], bh[3]);
            }
            if (c < 7) {
                char* sh = smem + SM_A + (size_t)(((c + 1) & 1) * 2 * ASZ) + s_off;
                char* sl = sh + ASZ;
#pragma unroll
                for (int q = 0; q < 4; q++) {
                    *(uint4*)(sh + q * 16) = rh[q];
                    *(uint4*)(sl + q * 16) = rl[q];
                }
            }
            __syncthreads();
        }

        {
            const int gr = mt * 16 + (lane >> 2);
            const int gc = nh * 16 + (lane & 3) * 2;
            *(float2*)&gbuf[gr * 32 + gc]           = make_float2(d0a[0] + d0b[0], d0a[1] + d0b[1]);
            *(float2*)&gbuf[(gr + 8) * 32 + gc]     = make_float2(d0a[2] + d0b[2], d0a[3] + d0b[3]);
            *(float2*)&gbuf[gr * 32 + gc + 8]       = make_float2(d1a[0] + d1b[0], d1a[1] + d1b[1]);
            *(float2*)&gbuf[(gr + 8) * 32 + gc + 8] = make_float2(d1a[2] + d1b[2], d1a[3] + d1b[3]);
        }
        __syncthreads();

#pragma unroll
        for (int cc = 0; cc < 2; cc++) {
            int cell = cc * 256 + tid;
            int b  = cell >> 3;
            int jj = cell & 7;
            size_t xb = ((size_t)(b * Tn + t)) * G4 + jbase + jj;
            float gi = gbuf[b * 32 +      jj] + g_xproj[xb];
            float gf = gbuf[b * 32 +  8 + jj] + g_xproj[xb + 1024];
            float gg = gbuf[b * 32 + 16 + jj] + g_xproj[xb + 2048];
            float go = gbuf[b * 32 + 24 + jj] + g_xproj[xb + 3072];
            float co = c_s[cell];
            float si = 1.f / (1.f + __expf(-gi));
            float sf = 1.f / (1.f + __expf(-gf));
            float so = 1.f / (1.f + __expf(-go));
            float tg = tanhf(gg);
            float cn = sf * co + si * tg;
            float hn = so * tanhf(cn);
            c_s[cell] = cn;

            size_t ob = ((size_t)(b * Tn + t)) * Hn + jbase + jj;
            out[ob] = hn;
            out[(size_t)BT * Hn + ob] = cn;

            __nv_bfloat16 hh = __float2bfloat16(hn);
            __nv_bfloat16 hl = __float2bfloat16(hn - __bfloat162float(hh));
            g_hhi[p ^ 1][b * Hn + jbase + jj] = hh;
            g_hlo[p ^ 1][b * Hn + jbase + jj] = hl;

            if (t == len_s[b] - 1) {
                out[(size_t)2 * BT * Hn + (size_t)b * Hn + jbase + jj] = hn;
                out[(size_t)2 * BT * Hn + (size_t)Bn * Hn + (size_t)b * Hn + jbase + jj] = cn;
            }
        }
        grid_sync();
        p ^= 1;
    }
}

// ---------------------------------------------------------------------------
extern "C" void kernel_launch(void* const* d_in, const int* in_sizes, int n_in,
                              void* d_out, int out_size)
{
    (void)in_sizes; (void)n_in; (void)out_size;
    const float* inputs = (const float*)d_in[0];
    const float* W_ih   = (const float*)d_in[1];
    const float* W_hh   = (const float*)d_in[2];
    const float* b_ih   = (const float*)d_in[3];
    const float* b_hh   = (const float*)d_in[4];
    const int*   length = (const int*)d_in[5];
    float* out = (float*)d_out;

    cudaFuncSetAttribute(xproj_mma_kernel,
                         cudaFuncAttributeMaxDynamicSharedMemorySize, XSM_TOTAL);
    cudaFuncSetAttribute(lstm_mma_kernel,
                         cudaFuncAttributeMaxDynamicSharedMemorySize, SM_TOTAL);

    __nv_bfloat16 *ahi, *alo, *whi, *wlo;
    cudaGetSymbolAddress((void**)&ahi, g_ahi);
    cudaGetSymbolAddress((void**)&alo, g_alo);
    cudaGetSymbolAddress((void**)&whi, g_whi);
    cudaGetSymbolAddress((void**)&wlo, g_wlo);

    const int nA4 = (BT * DIn) / 4;       // 4,194,304
    const int nW4 = (G4 * DIn) / 4;       // 524,288
    split_kernel<<<(nA4 + 255) / 256, 256>>>(inputs, ahi, alo, nA4);
    split_kernel<<<(nW4 + 255) / 256, 256>>>(W_ih, whi, wlo, nW4);

    dim3 gx(G4 / 64, BT / 128);           // 64 x 256, n fastest (A-tile L2 reuse)
    xproj_mma_kernel<<<gx, 256, XSM_TOTAL>>>(b_ih, b_hh);
    lstm_mma_kernel<<<NCTA, 256, SM_TOTAL>>>(W_hh, length, out);
}